// round 1
// baseline (speedup 1.0000x reference)
#include <cuda_runtime.h>

#define NU 200000
#define NI 100000
#define NN 300000
#define EE 9600000
#define SCAN_CHUNK 4096
#define NB_SCAN ((NN + SCAN_CHUNK - 1) / SCAN_CHUNK)   // 74 blocks

// ---- scratch (static device globals; no allocation in kernel_launch) ----
__device__ int    g_cnt[NN];
__device__ int    g_rowptr[NN + 1];
__device__ int    g_off[NN];
__device__ int    g_bsum[NB_SCAN];
__device__ int    g_scols[EE];
__device__ float  g_svals[EE];
__device__ float4 g_x[NN * 8];
__device__ float4 g_y[NN * 8];

// ---------------- CSR build ----------------
__global__ void k_zero() {
    int i = blockIdx.x * blockDim.x + threadIdx.x;
    if (i < NN) g_cnt[i] = 0;
}

__global__ void k_hist(const int* __restrict__ rows) {
    int e = blockIdx.x * blockDim.x + threadIdx.x;
    if (e < EE) atomicAdd(&g_cnt[rows[e]], 1);
}

__global__ void k_scan1() {
    __shared__ int sh[1024];
    int tid = threadIdx.x;
    int base = blockIdx.x * SCAN_CHUNK + tid * 4;
    int v[4];
    int run = 0;
#pragma unroll
    for (int i = 0; i < 4; i++) {
        int idx = base + i;
        int c = (idx < NN) ? g_cnt[idx] : 0;
        v[i] = run;
        run += c;
    }
    sh[tid] = run;
    __syncthreads();
    for (int off = 1; off < 1024; off <<= 1) {
        int t = (tid >= off) ? sh[tid - off] : 0;
        __syncthreads();
        sh[tid] += t;
        __syncthreads();
    }
    int pre = sh[tid] - run;  // exclusive prefix of this thread within block
#pragma unroll
    for (int i = 0; i < 4; i++) {
        int idx = base + i;
        if (idx < NN) g_rowptr[idx] = pre + v[i];
    }
    if (tid == 1023) g_bsum[blockIdx.x] = sh[1023];
}

__global__ void k_scan2() {
    if (threadIdx.x == 0) {
        int run = 0;
        for (int b = 0; b < NB_SCAN; b++) {
            int c = g_bsum[b];
            g_bsum[b] = run;
            run += c;
        }
        g_rowptr[NN] = EE;
    }
}

__global__ void k_scan3() {
    int i = blockIdx.x * blockDim.x + threadIdx.x;
    if (i < NN) {
        int v = g_rowptr[i] + g_bsum[i >> 12];  // 4096 = 2^12
        g_rowptr[i] = v;
        g_off[i]    = v;
    }
}

__global__ void k_scatter(const int* __restrict__ rows, const int* __restrict__ cols,
                          const float* __restrict__ vals) {
    int e = blockIdx.x * blockDim.x + threadIdx.x;
    if (e < EE) {
        int r = rows[e];
        int p = atomicAdd(&g_off[r], 1);
        g_scols[p] = cols[e];
        g_svals[p] = vals[e];
    }
}

// ---------------- init x0 and acc(=d_out) ----------------
__global__ void k_initx(const float4* __restrict__ uw, const float4* __restrict__ iw,
                        float4* __restrict__ out4) {
    int i = blockIdx.x * blockDim.x + threadIdx.x;
    if (i < NN * 8) {
        float4 v = (i < NU * 8) ? uw[i] : iw[i - NU * 8];
        g_x[i]  = v;
        out4[i] = v;
    }
}

// ---------------- SpMM: warp per row, 4 edges / iter, float4 lanes ----------------
// layer 0: x=g_x, y=g_y ; layer 1: x=g_y, y=g_x ; layer 2 (final): x=g_x, no y, *0.25
__global__ void __launch_bounds__(256) k_spmm(float4* __restrict__ out4, int layer) {
    int w = (blockIdx.x * 256 + threadIdx.x) >> 5;
    if (w >= NN) return;
    int lane = threadIdx.x & 31;
    int sub  = lane >> 3;   // which of 4 edges in the group
    int q    = lane & 7;    // which float4 chunk of the 32-float row

    const float4* __restrict__ x4 = (layer == 1) ? g_y : g_x;
    float4* __restrict__       y4 = (layer == 1) ? g_x : g_y;
    const int* __restrict__    sc = g_scols;
    const float* __restrict__  sv = g_svals;

    int s = g_rowptr[w];
    int e = g_rowptr[w + 1];

    float4 acc = make_float4(0.f, 0.f, 0.f, 0.f);
    int j = s;
    // main loop: 8 edges per iteration (two gather groups in flight)
    for (; j + 8 <= e; j += 8) {
        int   c0 = sc[j + sub];
        float v0 = sv[j + sub];
        int   c1 = sc[j + 4 + sub];
        float v1 = sv[j + 4 + sub];
        float4 a0 = x4[c0 * 8 + q];
        float4 a1 = x4[c1 * 8 + q];
        acc.x += v0 * a0.x + v1 * a1.x;
        acc.y += v0 * a0.y + v1 * a1.y;
        acc.z += v0 * a0.z + v1 * a1.z;
        acc.w += v0 * a0.w + v1 * a1.w;
    }
    // tail: groups of up to 4 edges, predicated
    for (; j < e; j += 4) {
        int je = j + sub;
        int c = 0;
        float v = 0.f;
        if (je < e) { c = sc[je]; v = sv[je]; }
        float4 a = x4[c * 8 + q];
        acc.x += v * a.x;
        acc.y += v * a.y;
        acc.z += v * a.z;
        acc.w += v * a.w;
    }
    // reduce across the 4 edge sub-groups (lanes with equal q)
    acc.x += __shfl_down_sync(0xffffffffu, acc.x, 16);
    acc.y += __shfl_down_sync(0xffffffffu, acc.y, 16);
    acc.z += __shfl_down_sync(0xffffffffu, acc.z, 16);
    acc.w += __shfl_down_sync(0xffffffffu, acc.w, 16);
    acc.x += __shfl_down_sync(0xffffffffu, acc.x, 8);
    acc.y += __shfl_down_sync(0xffffffffu, acc.y, 8);
    acc.z += __shfl_down_sync(0xffffffffu, acc.z, 8);
    acc.w += __shfl_down_sync(0xffffffffu, acc.w, 8);

    if (lane < 8) {
        float4 t = out4[w * 8 + lane];
        t.x += acc.x; t.y += acc.y; t.z += acc.z; t.w += acc.w;
        if (layer == 2) {
            t.x *= 0.25f; t.y *= 0.25f; t.z *= 0.25f; t.w *= 0.25f;
            out4[w * 8 + lane] = t;
        } else {
            out4[w * 8 + lane] = t;
            y4[w * 8 + lane]   = acc;
        }
    }
}

extern "C" void kernel_launch(void* const* d_in, const int* in_sizes, int n_in,
                              void* d_out, int out_size) {
    const int*    rows = (const int*)d_in[0];
    const int*    cols = (const int*)d_in[1];
    const float*  vals = (const float*)d_in[2];
    const float4* uw   = (const float4*)d_in[3];
    const float4* iw   = (const float4*)d_in[4];
    float4*       out4 = (float4*)d_out;

    (void)in_sizes; (void)n_in; (void)out_size;

    k_zero   <<<(NN + 255) / 256, 256>>>();
    k_hist   <<<(EE + 255) / 256, 256>>>(rows);
    k_scan1  <<<NB_SCAN, 1024>>>();
    k_scan2  <<<1, 32>>>();
    k_scan3  <<<(NN + 255) / 256, 256>>>();
    k_scatter<<<(EE + 255) / 256, 256>>>(rows, cols, vals);
    k_initx  <<<(NN * 8 + 255) / 256, 256>>>(uw, iw, out4);

    k_spmm<<<NN / 8, 256>>>(out4, 0);  // NN divisible by 8: 37500 blocks
    k_spmm<<<NN / 8, 256>>>(out4, 1);
    k_spmm<<<NN / 8, 256>>>(out4, 2);
}

// round 2
// speedup vs baseline: 1.1232x; 1.1232x over previous
#include <cuda_runtime.h>

#define NU 200000
#define NI 100000
#define NN 300000
#define EE 9600000
#define SCAN_CHUNK 4096
#define NB_SCAN ((NN + SCAN_CHUNK - 1) / SCAN_CHUNK)   // 74 blocks

// ---- scratch (static device globals; zero-initialized at module load) ----
__device__ int    g_cnt[NN];        // re-zeroed by k_scan1 each replay
__device__ int    g_rowptr[NN + 1];
__device__ int    g_off[NN];
__device__ int    g_bsum[NB_SCAN];
__device__ int2   g_edge[EE];       // packed {col, val_bits}
__device__ float4 g_x[NN * 8];      // x1 (layer0 out), gathered by layer1
__device__ float4 g_y[NN * 8];      // x2 (layer1 out), gathered by layer2

// ---------------- CSR build ----------------
__global__ void k_hist(const int* __restrict__ rows) {
    int e = blockIdx.x * blockDim.x + threadIdx.x;
    if (e < EE) atomicAdd(&g_cnt[rows[e]], 1);
}

__global__ void k_scan1() {
    __shared__ int sh[1024];
    int tid = threadIdx.x;
    int base = blockIdx.x * SCAN_CHUNK + tid * 4;
    int v[4];
    int run = 0;
#pragma unroll
    for (int i = 0; i < 4; i++) {
        int idx = base + i;
        int c = 0;
        if (idx < NN) { c = g_cnt[idx]; g_cnt[idx] = 0; }  // consume + re-zero for next replay
        v[i] = run;
        run += c;
    }
    sh[tid] = run;
    __syncthreads();
    for (int off = 1; off < 1024; off <<= 1) {
        int t = (tid >= off) ? sh[tid - off] : 0;
        __syncthreads();
        sh[tid] += t;
        __syncthreads();
    }
    int pre = sh[tid] - run;  // exclusive prefix within block
#pragma unroll
    for (int i = 0; i < 4; i++) {
        int idx = base + i;
        if (idx < NN) g_rowptr[idx] = pre + v[i];
    }
    if (tid == 1023) g_bsum[blockIdx.x] = sh[1023];
}

// fused scan2+scan3: each 256-thread block lies entirely inside one 4096-chunk,
// so one warp computes the prefix of block sums for that chunk.
__global__ void k_scan23() {
    __shared__ int s_base;
    int chunk = (int)((blockIdx.x * 256) >> 12);
    if (threadIdx.x < 32) {
        int s = 0;
        for (int b = threadIdx.x; b < chunk; b += 32) s += g_bsum[b];
#pragma unroll
        for (int o = 16; o; o >>= 1) s += __shfl_down_sync(0xffffffffu, s, o);
        if (threadIdx.x == 0) s_base = s;
    }
    __syncthreads();
    int i = blockIdx.x * 256 + threadIdx.x;
    if (i < NN) {
        int v = g_rowptr[i] + s_base;
        g_rowptr[i] = v;
        g_off[i]    = v;
    }
    if (i == 0) g_rowptr[NN] = EE;
}

__global__ void k_scatter(const int* __restrict__ rows, const int* __restrict__ cols,
                          const float* __restrict__ vals) {
    int e = blockIdx.x * blockDim.x + threadIdx.x;
    if (e < EE) {
        int r = rows[e];
        int p = atomicAdd(&g_off[r], 1);
        g_edge[p] = make_int2(cols[e], __float_as_int(vals[e]));
    }
}

// ---------------- SpMM: warp per row ----------------
// L=0: gather uw/iw          -> g_x = x1,  out = x0 + x1
// L=1: gather g_x            -> g_y = x2,  out += x2
// L=2: gather g_y            ->            out = (out + x3) * 0.25
__device__ __forceinline__ float4 gath0(const float4* __restrict__ uw,
                                        const float4* __restrict__ iw, int c, int q) {
    const float4* p = (c < NU) ? (uw + (size_t)c * 8) : (iw + (size_t)(c - NU) * 8);
    return p[q];
}

template <int L>
__global__ void __launch_bounds__(256) k_spmm(const float4* __restrict__ uw,
                                              const float4* __restrict__ iw,
                                              float4* __restrict__ out4) {
    int w = (blockIdx.x * 256 + threadIdx.x) >> 5;
    if (w >= NN) return;
    int lane = threadIdx.x & 31;
    int sub  = lane >> 3;   // which of 4 edges in the group
    int q    = lane & 7;    // which float4 chunk of the 32-float row

    const float4* __restrict__ x4 = (L == 1) ? g_x : g_y;  // L==0 unused
    const int2*   __restrict__ ed = g_edge;

    int s = g_rowptr[w];
    int e = g_rowptr[w + 1];

    float4 acc = make_float4(0.f, 0.f, 0.f, 0.f);
    int j = s;
    // main loop: 16 edges per iteration (4 gather groups in flight)
    for (; j + 16 <= e; j += 16) {
        int2 e0 = ed[j + sub];
        int2 e1 = ed[j + 4 + sub];
        int2 e2 = ed[j + 8 + sub];
        int2 e3 = ed[j + 12 + sub];
        float4 a0, a1, a2, a3;
        if (L == 0) {
            a0 = gath0(uw, iw, e0.x, q);
            a1 = gath0(uw, iw, e1.x, q);
            a2 = gath0(uw, iw, e2.x, q);
            a3 = gath0(uw, iw, e3.x, q);
        } else {
            a0 = x4[(size_t)e0.x * 8 + q];
            a1 = x4[(size_t)e1.x * 8 + q];
            a2 = x4[(size_t)e2.x * 8 + q];
            a3 = x4[(size_t)e3.x * 8 + q];
        }
        float v0 = __int_as_float(e0.y), v1 = __int_as_float(e1.y);
        float v2 = __int_as_float(e2.y), v3 = __int_as_float(e3.y);
        acc.x += v0 * a0.x + v1 * a1.x + v2 * a2.x + v3 * a3.x;
        acc.y += v0 * a0.y + v1 * a1.y + v2 * a2.y + v3 * a3.y;
        acc.z += v0 * a0.z + v1 * a1.z + v2 * a2.z + v3 * a3.z;
        acc.w += v0 * a0.w + v1 * a1.w + v2 * a2.w + v3 * a3.w;
    }
    // tail: groups of up to 4 edges, predicated
    for (; j < e; j += 4) {
        int je = j + sub;
        int c = 0;
        float v = 0.f;
        if (je < e) { int2 t = ed[je]; c = t.x; v = __int_as_float(t.y); }
        float4 a;
        if (L == 0) a = gath0(uw, iw, c, q);
        else        a = x4[(size_t)c * 8 + q];
        acc.x += v * a.x;
        acc.y += v * a.y;
        acc.z += v * a.z;
        acc.w += v * a.w;
    }
    // reduce across the 4 edge sub-groups (lanes sharing q)
#pragma unroll
    for (int o = 16; o >= 8; o >>= 1) {
        acc.x += __shfl_down_sync(0xffffffffu, acc.x, o);
        acc.y += __shfl_down_sync(0xffffffffu, acc.y, o);
        acc.z += __shfl_down_sync(0xffffffffu, acc.z, o);
        acc.w += __shfl_down_sync(0xffffffffu, acc.w, o);
    }

    if (lane < 8) {
        size_t oi = (size_t)w * 8 + lane;
        if (L == 0) {
            float4 x0 = (w < NU) ? uw[oi] : iw[(size_t)(w - NU) * 8 + lane];
            g_x[oi] = acc;
            out4[oi] = make_float4(x0.x + acc.x, x0.y + acc.y, x0.z + acc.z, x0.w + acc.w);
        } else if (L == 1) {
            float4 t = out4[oi];
            g_y[oi] = acc;
            out4[oi] = make_float4(t.x + acc.x, t.y + acc.y, t.z + acc.z, t.w + acc.w);
        } else {
            float4 t = out4[oi];
            out4[oi] = make_float4((t.x + acc.x) * 0.25f, (t.y + acc.y) * 0.25f,
                                   (t.z + acc.z) * 0.25f, (t.w + acc.w) * 0.25f);
        }
    }
}

extern "C" void kernel_launch(void* const* d_in, const int* in_sizes, int n_in,
                              void* d_out, int out_size) {
    const int*    rows = (const int*)d_in[0];
    const int*    cols = (const int*)d_in[1];
    const float*  vals = (const float*)d_in[2];
    const float4* uw   = (const float4*)d_in[3];
    const float4* iw   = (const float4*)d_in[4];
    float4*       out4 = (float4*)d_out;

    (void)in_sizes; (void)n_in; (void)out_size;

    k_hist   <<<(EE + 255) / 256, 256>>>(rows);
    k_scan1  <<<NB_SCAN, 1024>>>();
    k_scan23 <<<(NN + 255) / 256, 256>>>();
    k_scatter<<<(EE + 255) / 256, 256>>>(rows, cols, vals);

    k_spmm<0><<<NN / 8, 256>>>(uw, iw, out4);   // NN % 8 == 0 -> 37500 blocks
    k_spmm<1><<<NN / 8, 256>>>(uw, iw, out4);
    k_spmm<2><<<NN / 8, 256>>>(uw, iw, out4);
}